// round 12
// baseline (speedup 1.0000x reference)
#include <cuda_runtime.h>
#include <math_constants.h>

// x: (64, 4096, 256) fp32; top-8 over axis 1 (S), sorted desc -> (64, 8, 256)
#define B_DIM 64
#define S_DIM 4096
#define C_DIM 256
#define K_TOP 8

#define CHUNKS 16
#define CHUNK_S (S_DIM / CHUNKS)        // 256
#define PAIRS_PER_BLOCK 2               // 256 threads = 2 (b,chunk) pairs x 128 lanes
#define GRID1 (B_DIM * CHUNKS / PAIRS_PER_BLOCK)  // 512 blocks
#define HCHUNKS (CHUNKS / 2)            // 8 combined records per (b,c)

// Partials, layout [b][c][halfchunk][k]: 4 MiB static scratch.
// For fixed (b,c) the HCHUNKS*K_TOP=64 candidates are 256B contiguous.
__device__ __align__(256) float g_partial[B_DIM * C_DIM * HCHUNKS * K_TOP];

// Compare-exchange keeping max at 'a' (descending order).
__device__ __forceinline__ void ce(float& a, float& b) {
    float hi = fmaxf(a, b);
    float lo = fminf(a, b);
    a = hi; b = lo;
}

// Batcher odd-even mergesort, n=8, 19 CE, descending.
__device__ __forceinline__ void sort8_desc(float (&f)[8]) {
    ce(f[0],f[1]); ce(f[2],f[3]); ce(f[4],f[5]); ce(f[6],f[7]);
    ce(f[0],f[2]); ce(f[1],f[3]); ce(f[4],f[6]); ce(f[5],f[7]);
    ce(f[1],f[2]); ce(f[5],f[6]);
    ce(f[0],f[4]); ce(f[1],f[5]); ce(f[2],f[6]); ce(f[3],f[7]);
    ce(f[2],f[4]); ce(f[3],f[5]);
    ce(f[1],f[2]); ce(f[3],f[4]); ce(f[5],f[6]);
}

// Exact sorted top-8 of the union of two descending-sorted 8-lists.
__device__ __forceinline__ void merge8_desc(float (&t)[8], const float (&g)[8]) {
    #pragma unroll
    for (int i = 0; i < 8; ++i) t[i] = fmaxf(t[i], g[7 - i]);
    ce(t[0],t[4]); ce(t[1],t[5]); ce(t[2],t[6]); ce(t[3],t[7]);
    ce(t[0],t[2]); ce(t[1],t[3]); ce(t[4],t[6]); ce(t[5],t[7]);
    ce(t[0],t[1]); ce(t[2],t[3]); ce(t[4],t[5]); ce(t[6],t[7]);
}

// Pass 1: streaming loop identical to the R8-proven config. Tail: the two
// chunk-pairs in the block (adjacent chunks of the SAME batch) are merged
// through shared memory, halving partial traffic.
__global__ __launch_bounds__(256, 3) void kmax_partial_kernel(
    const float2* __restrict__ x2)
{
    __shared__ float s_xch[128][16];            // sub1's t0|t1 per lane (8 KB)

    const int sub  = threadIdx.x >> 7;          // 0..1
    const int lane = threadIdx.x & 127;         // float2 channel group
    const int pair = blockIdx.x * PAIRS_PER_BLOCK + sub;
    const int batch = pair >> 4;                // / CHUNKS
    const int chunk = pair & (CHUNKS - 1);

    const float2* __restrict__ p =
        x2 + ((size_t)batch * S_DIM + (size_t)chunk * CHUNK_S) * (C_DIM / 2) + lane;

    float t0[8], t1[8];
    #pragma unroll
    for (int i = 0; i < 8; ++i) { t0[i] = -CUDART_INF_F; t1[i] = -CUDART_INF_F; }

    #pragma unroll 1
    for (int s = 0; s < CHUNK_S; s += 16) {
        float2 buf[16];
        #pragma unroll
        for (int u = 0; u < 16; ++u)
            buf[u] = __ldcs(p + (size_t)(s + u) * (C_DIM / 2));

        float f[8], g[8];
        // channel .x
        #pragma unroll
        for (int u = 0; u < 8; ++u) { f[u] = buf[u].x; g[u] = buf[u + 8].x; }
        sort8_desc(f); sort8_desc(g);
        merge8_desc(f, g);      // f = sorted top-8 of the 16
        merge8_desc(t0, f);
        // channel .y
        #pragma unroll
        for (int u = 0; u < 8; ++u) { f[u] = buf[u].y; g[u] = buf[u + 8].y; }
        sort8_desc(f); sort8_desc(g);
        merge8_desc(f, g);
        merge8_desc(t1, f);
    }

    // Cross-sub merge: sub1 publishes, sub0 merges + stores combined record.
    if (sub == 1) {
        #pragma unroll
        for (int i = 0; i < 8; ++i) {
            s_xch[lane][i] = t0[i];
            s_xch[lane][8 + i] = t1[i];
        }
    }
    __syncthreads();
    if (sub == 0) {
        float g0[8], g1[8];
        #pragma unroll
        for (int i = 0; i < 8; ++i) {
            g0[i] = s_xch[lane][i];
            g1[i] = s_xch[lane][8 + i];
        }
        merge8_desc(t0, g0);
        merge8_desc(t1, g1);

        // Store: layout [b][c][halfchunk][k]; 64B contiguous per thread.
        const int hc = chunk >> 1;              // halfchunk = blockIdx.x & 7
        const int c0 = lane * 2;
        float4* o0 = (float4*)(g_partial
            + (((size_t)batch * C_DIM + c0) * HCHUNKS + hc) * K_TOP);
        float4* o1 = (float4*)(g_partial
            + (((size_t)batch * C_DIM + c0 + 1) * HCHUNKS + hc) * K_TOP);
        o0[0] = make_float4(t0[0], t0[1], t0[2], t0[3]);
        o0[1] = make_float4(t0[4], t0[5], t0[6], t0[7]);
        o1[0] = make_float4(t1[0], t1[1], t1[2], t1[3]);
        o1[1] = make_float4(t1[4], t1[5], t1[6], t1[7]);
    }
}

// Pass 2: warp = 4 (b,c) pairs, 8 lanes each. Lane owns 1 record (32B);
// warp reads 1 KB contiguous; 3 shuffle-xor merge levels (d=4,2,1).
__global__ __launch_bounds__(256) void kmax_merge_kernel(float* __restrict__ out)
{
    const int warp_id = (blockIdx.x * blockDim.x + threadIdx.x) >> 5;
    const int lane = threadIdx.x & 31;
    const int sg = lane >> 3;                   // sub-group 0..3
    const int sl = lane & 7;                    // lane within sub-group
    const int gp = warp_id * 4 + sg;            // global (b,c) pair
    const int b = gp >> 8;                      // / C_DIM
    const int c = gp & (C_DIM - 1);

    // Pair gp occupies 64 floats; lane's record = 8 consecutive floats.
    const float4* p4 = (const float4*)(g_partial + (size_t)gp * 64 + sl * 8);

    float v[8];
    {
        float4 a0 = p4[0], a1 = p4[1];
        v[0] = a0.x; v[1] = a0.y; v[2] = a0.z; v[3] = a0.w;
        v[4] = a1.x; v[5] = a1.y; v[6] = a1.z; v[7] = a1.w;
    }

    #pragma unroll
    for (int d = 4; d >= 1; d >>= 1) {
        float h[8];
        #pragma unroll
        for (int i = 0; i < 8; ++i)
            h[i] = __shfl_xor_sync(0xFFFFFFFFu, v[i], d);
        merge8_desc(v, h);
    }

    out[((size_t)b * K_TOP + sl) * C_DIM + c] = v[sl];
}

extern "C" void kernel_launch(void* const* d_in, const int* in_sizes, int n_in,
                              void* d_out, int out_size) {
    const float2* x2 = (const float2*)d_in[0];
    float* out = (float*)d_out;

    kmax_partial_kernel<<<GRID1, 256>>>(x2);
    // 16384 pairs / 4 per warp = 4096 warps = 512 blocks x 8 warps.
    kmax_merge_kernel<<<512, 256>>>(out);
}

// round 13
// speedup vs baseline: 1.0328x; 1.0328x over previous
#include <cuda_runtime.h>
#include <math_constants.h>

// x: (64, 4096, 256) fp32; top-8 over axis 1 (S), sorted desc -> (64, 8, 256)
#define B_DIM 64
#define S_DIM 4096
#define C_DIM 256
#define K_TOP 8

#define CHUNKS 16
#define CHUNK_S (S_DIM / CHUNKS)        // 256
#define PAIRS_PER_BLOCK 2               // 256 threads = 2 (b,chunk) pairs x 128 lanes
#define GRID1 (B_DIM * CHUNKS / PAIRS_PER_BLOCK)  // 512 blocks

// Partials, layout [b][c][chunk][k]: 8 MiB static scratch.
// For fixed (b,c) the CHUNKS*K_TOP=128 candidates are 512B contiguous.
__device__ __align__(256) float g_partial[B_DIM * C_DIM * CHUNKS * K_TOP];

// Compare-exchange keeping max at 'a' (descending order).
__device__ __forceinline__ void ce(float& a, float& b) {
    float hi = fmaxf(a, b);
    float lo = fminf(a, b);
    a = hi; b = lo;
}

// Batcher odd-even mergesort, n=8, 19 CE, descending.
__device__ __forceinline__ void sort8_desc(float (&f)[8]) {
    ce(f[0],f[1]); ce(f[2],f[3]); ce(f[4],f[5]); ce(f[6],f[7]);
    ce(f[0],f[2]); ce(f[1],f[3]); ce(f[4],f[6]); ce(f[5],f[7]);
    ce(f[1],f[2]); ce(f[5],f[6]);
    ce(f[0],f[4]); ce(f[1],f[5]); ce(f[2],f[6]); ce(f[3],f[7]);
    ce(f[2],f[4]); ce(f[3],f[5]);
    ce(f[1],f[2]); ce(f[3],f[4]); ce(f[5],f[6]);
}

// Exact sorted top-8 of the union of two descending-sorted 8-lists.
__device__ __forceinline__ void merge8_desc(float (&t)[8], const float (&g)[8]) {
    #pragma unroll
    for (int i = 0; i < 8; ++i) t[i] = fmaxf(t[i], g[7 - i]);
    ce(t[0],t[4]); ce(t[1],t[5]); ce(t[2],t[6]); ce(t[3],t[7]);
    ce(t[0],t[2]); ce(t[1],t[3]); ce(t[4],t[6]); ce(t[5],t[7]);
    ce(t[0],t[1]); ce(t[2],t[3]); ce(t[4],t[5]); ce(t[6],t[7]);
}

// Pass 1 (R8-proven, untouched): block = 2 (batch,chunk) pairs; 128 lanes x
// float2 = 256 channels; 16 batched LDG.64 per iteration.
__global__ __launch_bounds__(256, 3) void kmax_partial_kernel(
    const float2* __restrict__ x2)
{
    const int sub  = threadIdx.x >> 7;          // 0..1
    const int lane = threadIdx.x & 127;         // float2 channel group
    const int pair = blockIdx.x * PAIRS_PER_BLOCK + sub;
    const int batch = pair >> 4;                // / CHUNKS
    const int chunk = pair & (CHUNKS - 1);

    const float2* __restrict__ p =
        x2 + ((size_t)batch * S_DIM + (size_t)chunk * CHUNK_S) * (C_DIM / 2) + lane;

    float t0[8], t1[8];
    #pragma unroll
    for (int i = 0; i < 8; ++i) { t0[i] = -CUDART_INF_F; t1[i] = -CUDART_INF_F; }

    #pragma unroll 1
    for (int s = 0; s < CHUNK_S; s += 16) {
        float2 buf[16];
        #pragma unroll
        for (int u = 0; u < 16; ++u)
            buf[u] = __ldcs(p + (size_t)(s + u) * (C_DIM / 2));

        float f[8], g[8];
        // channel .x
        #pragma unroll
        for (int u = 0; u < 8; ++u) { f[u] = buf[u].x; g[u] = buf[u + 8].x; }
        sort8_desc(f); sort8_desc(g);
        merge8_desc(f, g);      // f = sorted top-8 of the 16
        merge8_desc(t0, f);
        // channel .y
        #pragma unroll
        for (int u = 0; u < 8; ++u) { f[u] = buf[u].y; g[u] = buf[u + 8].y; }
        sort8_desc(f); sort8_desc(g);
        merge8_desc(f, g);
        merge8_desc(t1, f);
    }

    // Store: layout [b][c][chunk][k]; 64B contiguous per thread (4x STG.128).
    const int c0 = lane * 2;
    float4* __restrict__ o0 = (float4*)(g_partial
        + (((size_t)batch * C_DIM + c0) * CHUNKS + chunk) * K_TOP);
    float4* __restrict__ o1 = (float4*)(g_partial
        + (((size_t)batch * C_DIM + c0 + 1) * CHUNKS + chunk) * K_TOP);
    o0[0] = make_float4(t0[0], t0[1], t0[2], t0[3]);
    o0[1] = make_float4(t0[4], t0[5], t0[6], t0[7]);
    o1[0] = make_float4(t1[0], t1[1], t1[2], t1[3]);
    o1[1] = make_float4(t1[4], t1[5], t1[6], t1[7]);
}

// Pass 2: 4 threads per (b,c) pair. Thread batches 8 LDG.128 (its 4 records,
// 128B; warp reads 4KB contiguous), chains 3 local merge8s, then 2 shuffle
// levels (xor 1, 2). High MLP, short dependency chain.
__global__ __launch_bounds__(256) void kmax_merge_kernel(float* __restrict__ out)
{
    const int tid = blockIdx.x * blockDim.x + threadIdx.x;
    const int gp = tid >> 2;                    // global (b,c) pair
    const int j  = tid & 3;                     // sub-lane within pair
    const int b = gp >> 8;                      // / C_DIM
    const int c = gp & (C_DIM - 1);

    // Pair gp = 128 floats; thread j owns records 4j..4j+3 = 32 floats = 128B.
    const float4* __restrict__ p4 =
        (const float4*)(g_partial + (size_t)gp * 128 + j * 32);

    float4 r[8];
    #pragma unroll
    for (int i = 0; i < 8; ++i) r[i] = p4[i];   // 8 batched LDG.128

    float v[8], g[8];
    v[0] = r[0].x; v[1] = r[0].y; v[2] = r[0].z; v[3] = r[0].w;
    v[4] = r[1].x; v[5] = r[1].y; v[6] = r[1].z; v[7] = r[1].w;
    #pragma unroll
    for (int rec = 1; rec < 4; ++rec) {
        g[0] = r[2*rec].x;   g[1] = r[2*rec].y;
        g[2] = r[2*rec].z;   g[3] = r[2*rec].w;
        g[4] = r[2*rec+1].x; g[5] = r[2*rec+1].y;
        g[6] = r[2*rec+1].z; g[7] = r[2*rec+1].w;
        merge8_desc(v, g);
    }

    // 2 shuffle-xor levels across the 4 threads of the pair.
    #pragma unroll
    for (int d = 1; d <= 2; d <<= 1) {
        float h[8];
        #pragma unroll
        for (int i = 0; i < 8; ++i)
            h[i] = __shfl_xor_sync(0xFFFFFFFFu, v[i], d);
        merge8_desc(v, h);
    }

    // All 4 threads hold the sorted top-8; thread j writes k = 2j, 2j+1.
    out[((size_t)b * K_TOP + 2*j)     * C_DIM + c] = v[2*j];
    out[((size_t)b * K_TOP + 2*j + 1) * C_DIM + c] = v[2*j + 1];
}

extern "C" void kernel_launch(void* const* d_in, const int* in_sizes, int n_in,
                              void* d_out, int out_size) {
    const float2* x2 = (const float2*)d_in[0];
    float* out = (float*)d_out;

    kmax_partial_kernel<<<GRID1, 256>>>(x2);
    // 16384 pairs x 4 threads = 65536 threads = 256 blocks x 256.
    kmax_merge_kernel<<<256, 256>>>(out);
}